// round 12
// baseline (speedup 1.0000x reference)
#include <cuda_runtime.h>

#define Bsz   32768
#define Lq    7
#define NSTEP 5
#define M1    (Bsz*NSTEP)          /* 163840 rows (b,t) t<5 */
#define BLq   (Bsz*Lq)             /* 229376 */
#define NEGV  -1000000000.0f

// ------------- static device scratch (no allocation APIs anywhere) -------------
static __device__ float g_E  [(size_t)M1 * 256];   // edges
static __device__ float g_Z  [(size_t)M1 * 256];   // edge @ W_edge^T
static __device__ float g_qt [(size_t)Bsz * 256];
static __device__ float g_inp[(size_t)Bsz * 256];
static __device__ float g_ctx[(size_t)BLq * 256];  // (b*7+l, h)
static __device__ float g_att[BLq];
static __device__ float g_cmax[Lq];
static __device__ float g_csum[Lq];
static __device__ int   g_x64;                     // 1 if xes is int64 on device

// ------------- XLA/Eigen f32 tanh (rational approx, clamp 7.90531110763549805) ---
__device__ __forceinline__ float xtanh(float x) {
    float ax = fabsf(x);
    if (ax < 0.0004f) return x;
    float cx = fminf(fmaxf(x, -7.90531110763549805f), 7.90531110763549805f);
    float x2 = cx * cx;
    float p = fmaf(x2, -2.76076847742355e-16f, 2.00018790482477e-13f);
    p = fmaf(p, x2, -8.60467152213735e-11f);
    p = fmaf(p, x2,  5.12229709037114e-08f);
    p = fmaf(p, x2,  1.48572235717979e-05f);
    p = fmaf(p, x2,  6.37261928875436e-04f);
    p = fmaf(p, x2,  4.89352455891786e-03f);
    p = cx * p;
    float q = fmaf(x2, 1.19825839466702e-06f, 1.18534705686654e-04f);
    q = fmaf(q, x2, 2.26843463243900e-03f);
    q = fmaf(q, x2, 4.89352518554385e-03f);
    return __fdiv_rn(p, q);
}

// ------------- threefry2x32, key = (0, 42), 20 rounds ------------------------
#define TFR(r) { x0 += x1; x1 = (x1 << (r)) | (x1 >> (32 - (r))); x1 ^= x0; }
__device__ __forceinline__ void threefry42(unsigned c0, unsigned c1,
                                           unsigned& o0, unsigned& o1) {
    const unsigned ks0 = 0u, ks1 = 42u, ks2 = 0x1BD11BDAu ^ 0u ^ 42u;
    unsigned x0 = c0 + ks0, x1 = c1 + ks1;
    TFR(13) TFR(15) TFR(26) TFR(6)   x0 += ks1; x1 += ks2 + 1u;
    TFR(17) TFR(29) TFR(16) TFR(24)  x0 += ks2; x1 += ks0 + 2u;
    TFR(13) TFR(15) TFR(26) TFR(6)   x0 += ks0; x1 += ks1 + 3u;
    TFR(17) TFR(29) TFR(16) TFR(24)  x0 += ks1; x1 += ks2 + 4u;
    TFR(13) TFR(15) TFR(26) TFR(6)   x0 += ks2; x1 += ks0 + 5u;
    o0 = x0; o1 = x1;
}

// hypothesis: jax >= 0.5 default threefry_partitionable=True:
// bits[j] = o0 ^ o1 of threefry(key, (hi=0, lo=j)).  (Set to 0 to use the
// legacy split-halves scheme next round if rel_err says the stream is wrong.)
#define PARTITIONABLE 1
__device__ __forceinline__ unsigned jax_bits(unsigned j) {
    unsigned o0, o1;
#if PARTITIONABLE
    threefry42(0u, j, o0, o1);
    return o0 ^ o1;
#else
    const unsigned half = BLq / 2;
    if (j < half) { threefry42(j, j + half, o0, o1); return o0; }
    else          { threefry42(j - half, j, o0, o1); return o1; }
#endif
}

// ------------- detect xes element width (int64 vs int32) ----------------------
__global__ void detect_kernel(const unsigned* __restrict__ x) {
    if (threadIdx.x == 0 && blockIdx.x == 0) {
        int a = 1;
        for (int k = 0; k < 256; k++)
            if (x[2 * k + 1] != 0u) { a = 0; break; }
        g_x64 = a;
    }
}

// ------------- G1: edge pass. K=512 zero-padded concat keeps each 256-chain
//               bit-identical to a standalone ascending-k f32 gemm chain. -----
// xcol=0: A row = enc[h_idx]; weights seg0=W_h (cond), seg1=Ws_h (else); write E
// xcol=1: A row = enc[v_idx]; weights seg0=W_v, seg1=Ws_v; E += result
__global__ void __launch_bounds__(256)
edge_gemm(const float* __restrict__ enc, const void* __restrict__ xraw,
          const float* __restrict__ Wc, const float* __restrict__ We,
          int xcol, int addmode) {
    __shared__ float As[8][128];
    __shared__ float Wsm[8][128];
    __shared__ const float* Ap[128];
    __shared__ int segm[128];
    const int tid  = threadIdx.x;
    const int row0 = blockIdx.x * 128;
    const int col0 = blockIdx.y * 128;
    if (tid < 128) {
        int r = row0 + tid;
        int b = r / 5, t = r - b * 5;
        int vi, tv;
        if (g_x64) {
            const long long* xp = (const long long*)xraw + ((size_t)b * 6 + t) * 3;
            vi = (int)xp[xcol]; tv = (int)xp[2];
        } else {
            const int* xp = (const int*)xraw + ((size_t)b * 6 + t) * 3;
            vi = xp[xcol]; tv = xp[2];
        }
        Ap[tid]   = enc + ((size_t)b * 7 + vi) * 256;
        segm[tid] = (tv == 0) ? 0 : 1;
    }
    __syncthreads();
    const int li = tid >> 1, lk = (tid & 1) * 4;
    const int ty = tid >> 4, tx = tid & 15;
    const float* ap = Ap[li];
    const int myseg = segm[li];
    float acc[8][8];
#pragma unroll
    for (int i = 0; i < 8; i++)
#pragma unroll
        for (int j = 0; j < 8; j++) acc[i][j] = 0.f;

    for (int k0 = 0; k0 < 512; k0 += 8) {
        int sg = k0 >> 8;
        float4 av;
        if (sg == myseg) av = *(const float4*)(ap + (k0 & 255) + lk);
        else             av = make_float4(0.f, 0.f, 0.f, 0.f);
        const float* Wm = sg ? We : Wc;
        float4 wv = *(const float4*)(Wm + (size_t)(col0 + li) * 256 + (k0 & 255) + lk);
        As [lk+0][li] = av.x; As [lk+1][li] = av.y; As [lk+2][li] = av.z; As [lk+3][li] = av.w;
        Wsm[lk+0][li] = wv.x; Wsm[lk+1][li] = wv.y; Wsm[lk+2][li] = wv.z; Wsm[lk+3][li] = wv.w;
        __syncthreads();
#pragma unroll
        for (int k = 0; k < 8; k++) {
            float a[8], w[8];
            *(float4*)(a)     = *(const float4*)&As[k][ty * 8];
            *(float4*)(a + 4) = *(const float4*)&As[k][ty * 8 + 4];
            *(float4*)(w)     = *(const float4*)&Wsm[k][tx * 8];
            *(float4*)(w + 4) = *(const float4*)&Wsm[k][tx * 8 + 4];
#pragma unroll
            for (int i = 0; i < 8; i++)
#pragma unroll
                for (int j = 0; j < 8; j++)
                    acc[i][j] = fmaf(a[i], w[j], acc[i][j]);
        }
        __syncthreads();
    }
#pragma unroll
    for (int i = 0; i < 8; i++) {
        float* cp = g_E + (size_t)(row0 + ty * 8 + i) * 256 + col0 + tx * 8;
        if (addmode) {
            float4 c0 = *(float4*)cp, c1 = *(float4*)(cp + 4);
            c0.x += acc[i][0]; c0.y += acc[i][1]; c0.z += acc[i][2]; c0.w += acc[i][3];
            c1.x += acc[i][4]; c1.y += acc[i][5]; c1.z += acc[i][6]; c1.w += acc[i][7];
            *(float4*)cp = c0; *(float4*)(cp + 4) = c1;
        } else {
            *(float4*)cp       = make_float4(acc[i][0], acc[i][1], acc[i][2], acc[i][3]);
            *(float4*)(cp + 4) = make_float4(acc[i][4], acc[i][5], acc[i][6], acc[i][7]);
        }
    }
}

// ------------- generic C = A @ W^T (+bias), K=256, ascending-k chain ----------
__global__ void __launch_bounds__(256)
gemm256(const float* __restrict__ A, const float* __restrict__ W,
        const float* __restrict__ bias, float* __restrict__ C) {
    __shared__ float As[8][128];
    __shared__ float Wsm[8][128];
    const int tid  = threadIdx.x;
    const int row0 = blockIdx.x * 128;
    const int col0 = blockIdx.y * 128;
    const int li = tid >> 1, lk = (tid & 1) * 4;
    const int ty = tid >> 4, tx = tid & 15;
    float acc[8][8];
#pragma unroll
    for (int i = 0; i < 8; i++)
#pragma unroll
        for (int j = 0; j < 8; j++) acc[i][j] = 0.f;
    const float* ap = A + (size_t)(row0 + li) * 256 + lk;
    const float* wp = W + (size_t)(col0 + li) * 256 + lk;
    for (int k0 = 0; k0 < 256; k0 += 8) {
        float4 av = *(const float4*)(ap + k0);
        float4 wv = *(const float4*)(wp + k0);
        As [lk+0][li] = av.x; As [lk+1][li] = av.y; As [lk+2][li] = av.z; As [lk+3][li] = av.w;
        Wsm[lk+0][li] = wv.x; Wsm[lk+1][li] = wv.y; Wsm[lk+2][li] = wv.z; Wsm[lk+3][li] = wv.w;
        __syncthreads();
#pragma unroll
        for (int k = 0; k < 8; k++) {
            float a[8], w[8];
            *(float4*)(a)     = *(const float4*)&As[k][ty * 8];
            *(float4*)(a + 4) = *(const float4*)&As[k][ty * 8 + 4];
            *(float4*)(w)     = *(const float4*)&Wsm[k][tx * 8];
            *(float4*)(w + 4) = *(const float4*)&Wsm[k][tx * 8 + 4];
#pragma unroll
            for (int i = 0; i < 8; i++)
#pragma unroll
                for (int j = 0; j < 8; j++)
                    acc[i][j] = fmaf(a[i], w[j], acc[i][j]);
        }
        __syncthreads();
    }
    float bj[8];
#pragma unroll
    for (int j = 0; j < 8; j++) bj[j] = bias ? bias[col0 + tx * 8 + j] : 0.f;
#pragma unroll
    for (int i = 0; i < 8; i++) {
        float* cp = C + (size_t)(row0 + ty * 8 + i) * 256 + col0 + tx * 8;
        *(float4*)cp       = make_float4(acc[i][0]+bj[0], acc[i][1]+bj[1], acc[i][2]+bj[2], acc[i][3]+bj[3]);
        *(float4*)(cp + 4) = make_float4(acc[i][4]+bj[4], acc[i][5]+bj[5], acc[i][6]+bj[6], acc[i][7]+bj[7]);
    }
}

// ------------- qt = relu(E[b,4] + max(0, Z[b,0..4])) --------------------------
__global__ void qt_kernel() {
    int i = blockIdx.x * 256 + threadIdx.x;     // over Bsz*256
    int b = i >> 8, h = i & 255;
    const float* zp = g_Z + (size_t)b * 5 * 256 + h;
    float st = fmaxf(0.f, zp[0]);
    st = fmaxf(st, zp[256]);
    st = fmaxf(st, zp[512]);
    st = fmaxf(st, zp[768]);
    st = fmaxf(st, zp[1024]);
    float e4 = g_E[(size_t)(b * 5 + 4) * 256 + h];
    g_qt[i] = fmaxf(e4 + st, 0.f);
}

// ------------- att[b,l] = 10*tanh(where(mask, sum_h V*tanh(inp+ctx), NEG)) ----
// One warp per (b,l); lanes stride h by 32 (XLA row-reduce pattern),
// then shfl_down 16..1 combine.
__global__ void __launch_bounds__(256)
att_kernel(const int* __restrict__ mask, const float* __restrict__ V) {
    int warp = blockIdx.x * 8 + (threadIdx.x >> 5);
    int lane = threadIdx.x & 31;
    int b = warp / 7;
    const float* ctxr = g_ctx + (size_t)warp * 256;
    const float* inpr = g_inp + (size_t)b * 256;
    float s = 0.f;
#pragma unroll
    for (int i = 0; i < 8; i++) {
        int h = i * 32 + lane;
        s += V[h] * xtanh(inpr[h] + ctxr[h]);
    }
#pragma unroll
    for (int off = 16; off > 0; off >>= 1)
        s += __shfl_down_sync(0xffffffffu, s, off);
    if (lane == 0) {
        float a = mask[warp] ? s : NEGV;
        g_att[warp] = 10.0f * xtanh(a);
    }
}

// ------------- per-column (axis=0) max and exp-sum ----------------------------
__global__ void colred() {
    int l = blockIdx.x, tid = threadIdx.x;
    __shared__ float red[256];
    float m = -3.4e38f;
    for (int b = tid; b < Bsz; b += 256) m = fmaxf(m, g_att[b * 7 + l]);
    red[tid] = m; __syncthreads();
    for (int s = 128; s > 0; s >>= 1) {
        if (tid < s) red[tid] = fmaxf(red[tid], red[tid + s]);
        __syncthreads();
    }
    float cm = red[0]; __syncthreads();
    float su = 0.f;
    for (int b = tid; b < Bsz; b += 256) su += expf(g_att[b * 7 + l] - cm);
    red[tid] = su; __syncthreads();
    for (int s = 128; s > 0; s >>= 1) {
        if (tid < s) red[tid] += red[tid + s];
        __syncthreads();
    }
    if (tid == 0) { g_cmax[l] = cm; g_csum[l] = red[0]; }
}

// ------------- alpha, gumbel, argmax, outputs ---------------------------------
__global__ void sample_kernel(const int* __restrict__ mask, float* __restrict__ out) {
    int b = blockIdx.x * 256 + threadIdx.x;
    if (b >= Bsz) return;
    float alpha[7], y[7];
#pragma unroll
    for (int l = 0; l < Lq; l++) {
        float e = expf(g_att[b * 7 + l] - g_cmax[l]);
        alpha[l] = __fdiv_rn(e, g_csum[l]);
        unsigned bits = jax_bits((unsigned)(b * 7 + l));
        float f = __uint_as_float((bits >> 9) | 0x3f800000u) - 1.0f;
        float u = (f > 0.f) ? f : 1.17549435e-38f;     // jax uniform [tiny, 1)
        float g = -logf(-logf(u));
        y[l] = g + logf(alpha[l]);
    }
    int idx = 0; float best = y[0];
#pragma unroll
    for (int l = 1; l < Lq; l++)
        if (y[l] > best) { best = y[l]; idx = l; }     // first-max like jnp.argmax
    out[b]        = (float)idx;
    out[Bsz + b]  = alpha[idx];
#pragma unroll
    for (int l = 0; l < Lq; l++)
        out[2 * Bsz + (size_t)b * 7 + l] = (float)(mask[b * 7 + l] - (l == idx ? 1 : 0));
}

// ------------- launch ---------------------------------------------------------
extern "C" void kernel_launch(void* const* d_in, const int* in_sizes, int n_in,
                              void* d_out, int out_size) {
    const float* enc  = (const float*)d_in[0];
    const void*  xes  = d_in[1];
    const int*   mask = (const int*)d_in[2];
    const float* Wh   = (const float*)d_in[3];
    const float* Wv   = (const float*)d_in[4];
    const float* Wsh  = (const float*)d_in[5];
    const float* Wsv  = (const float*)d_in[6];
    const float* We   = (const float*)d_in[7];
    const float* Win  = (const float*)d_in[8];
    const float* bin  = (const float*)d_in[9];
    const float* Wctx = (const float*)d_in[10];
    const float* bctx = (const float*)d_in[11];
    const float* V    = (const float*)d_in[12];
    float* out = (float*)d_out;

    float *pE, *pZ, *pqt, *pinp, *pctx;
    cudaGetSymbolAddress((void**)&pE,   g_E);
    cudaGetSymbolAddress((void**)&pZ,   g_Z);
    cudaGetSymbolAddress((void**)&pqt,  g_qt);
    cudaGetSymbolAddress((void**)&pinp, g_inp);
    cudaGetSymbolAddress((void**)&pctx, g_ctx);

    detect_kernel<<<1, 32>>>((const unsigned*)xes);

    dim3 gE(M1 / 128, 2);
    edge_gemm<<<gE, 256>>>(enc, xes, Wh, Wsh, 0, 0);   // h-side
    edge_gemm<<<gE, 256>>>(enc, xes, Wv, Wsv, 1, 1);   // v-side, E += ...

    gemm256<<<dim3(M1 / 128, 2), 256>>>(pE, We, nullptr, pZ);        // Z = E @ We^T
    qt_kernel<<<Bsz, 256>>>();
    gemm256<<<dim3(Bsz / 128, 2), 256>>>(pqt, Win, bin, pinp);       // inp
    gemm256<<<dim3(BLq / 128, 2), 256>>>(enc, Wctx, bctx, pctx);     // ctx
    att_kernel<<<BLq / 8, 256>>>(mask, V);
    colred<<<Lq, 256>>>();
    sample_kernel<<<Bsz / 256, 256>>>(mask, out);
}

// round 13
// speedup vs baseline: 1.7251x; 1.7251x over previous
#include <cuda_runtime.h>

#define Bsz   32768
#define Lq    7
#define NSTEP 5
#define M1    (Bsz*NSTEP)          /* 163840 rows (b,t) t<5 */
#define BLq   (Bsz*Lq)             /* 229376 */
#define NEGV  -1000000000.0f
#define NBLK  640                  /* M1/256 */

// ------------- static device scratch (no allocation APIs anywhere) -------------
static __device__ float g_E  [(size_t)M1 * 256];   // edges
static __device__ float g_Z  [(size_t)M1 * 256];   // edge @ W_edge^T
static __device__ float g_qt [(size_t)Bsz * 256];
static __device__ float g_inp[(size_t)Bsz * 256];
static __device__ float g_ctx[(size_t)BLq * 256];  // (b*7+l, h)
static __device__ float g_att[BLq];
static __device__ float g_cmax[Lq];
static __device__ float g_csum[Lq];
static __device__ int   g_x64;                     // 1 if xes is int64 on device
static __device__ int   g_cntA[NBLK];              // per-block cond counts -> exclusive scan
static __device__ int   g_nA;                      // total cond rows
static __device__ int   g_perm[M1];                // bucket A rows [0,nA), bucket B [nA,M1)

// ------------- XLA/Eigen f32 tanh (rational approx, clamp 7.90531110763549805) ---
__device__ __forceinline__ float xtanh(float x) {
    float ax = fabsf(x);
    if (ax < 0.0004f) return x;
    float cx = fminf(fmaxf(x, -7.90531110763549805f), 7.90531110763549805f);
    float x2 = cx * cx;
    float p = fmaf(x2, -2.76076847742355e-16f, 2.00018790482477e-13f);
    p = fmaf(p, x2, -8.60467152213735e-11f);
    p = fmaf(p, x2,  5.12229709037114e-08f);
    p = fmaf(p, x2,  1.48572235717979e-05f);
    p = fmaf(p, x2,  6.37261928875436e-04f);
    p = fmaf(p, x2,  4.89352455891786e-03f);
    p = cx * p;
    float q = fmaf(x2, 1.19825839466702e-06f, 1.18534705686654e-04f);
    q = fmaf(q, x2, 2.26843463243900e-03f);
    q = fmaf(q, x2, 4.89352518554385e-03f);
    return __fdiv_rn(p, q);
}

// ------------- threefry2x32, key = (0, 42), 20 rounds ------------------------
#define TFR(r) { x0 += x1; x1 = (x1 << (r)) | (x1 >> (32 - (r))); x1 ^= x0; }
__device__ __forceinline__ void threefry42(unsigned c0, unsigned c1,
                                           unsigned& o0, unsigned& o1) {
    const unsigned ks0 = 0u, ks1 = 42u, ks2 = 0x1BD11BDAu ^ 0u ^ 42u;
    unsigned x0 = c0 + ks0, x1 = c1 + ks1;
    TFR(13) TFR(15) TFR(26) TFR(6)   x0 += ks1; x1 += ks2 + 1u;
    TFR(17) TFR(29) TFR(16) TFR(24)  x0 += ks2; x1 += ks0 + 2u;
    TFR(13) TFR(15) TFR(26) TFR(6)   x0 += ks0; x1 += ks1 + 3u;
    TFR(17) TFR(29) TFR(16) TFR(24)  x0 += ks1; x1 += ks2 + 4u;
    TFR(13) TFR(15) TFR(26) TFR(6)   x0 += ks2; x1 += ks0 + 5u;
    o0 = x0; o1 = x1;
}

__device__ __forceinline__ unsigned jax_bits(unsigned j) {
    unsigned o0, o1;
    threefry42(0u, j, o0, o1);      // partitionable threefry: bits = o0 ^ o1
    return o0 ^ o1;
}

// ------------- xes fetch (int64 vs int32, detected on device) ------------------
__device__ __forceinline__ void fetch_x(const void* xraw, int b, int t,
                                        int& hi, int& vi, int& tv) {
    if (g_x64) {
        const long long* xp = (const long long*)xraw + ((size_t)b * 6 + t) * 3;
        hi = (int)xp[0]; vi = (int)xp[1]; tv = (int)xp[2];
    } else {
        const int* xp = (const int*)xraw + ((size_t)b * 6 + t) * 3;
        hi = xp[0]; vi = xp[1]; tv = xp[2];
    }
}

__global__ void detect_kernel(const unsigned* __restrict__ x) {
    if (threadIdx.x == 0 && blockIdx.x == 0) {
        int a = 1;
        for (int k = 0; k < 256; k++)
            if (x[2 * k + 1] != 0u) { a = 0; break; }
        g_x64 = a;
    }
}

// ------------- bucketing: partition rows r=b*5+t by cond=(t_val==0) -----------
__global__ void bcount(const void* __restrict__ xraw) {
    int tid = threadIdx.x, blk = blockIdx.x;
    int r = blk * 256 + tid;
    int b = r / 5, t = r - b * 5;
    int hi, vi, tv; fetch_x(xraw, b, t, hi, vi, tv);
    int c = __syncthreads_count(tv == 0);
    if (tid == 0) g_cntA[blk] = c;
}

__global__ void bscan() {
    __shared__ int s[1024];
    int tid = threadIdx.x;
    int v = (tid < NBLK) ? g_cntA[tid] : 0;
    s[tid] = v; __syncthreads();
    for (int off = 1; off < 1024; off <<= 1) {
        int t = (tid >= off) ? s[tid - off] : 0;
        __syncthreads();
        s[tid] += t; __syncthreads();
    }
    if (tid < NBLK) g_cntA[tid] = s[tid] - v;     // exclusive
    if (tid == NBLK - 1) g_nA = s[tid];
}

__global__ void bscatter(const void* __restrict__ xraw) {
    int tid = threadIdx.x, blk = blockIdx.x;
    int r = blk * 256 + tid;
    int b = r / 5, t = r - b * 5;
    int hi, vi, tv; fetch_x(xraw, b, t, hi, vi, tv);
    bool cond = (tv == 0);
    unsigned m = __ballot_sync(0xffffffffu, cond);
    int lane = tid & 31, w = tid >> 5;
    __shared__ int wA[8], wOffA[8];
    int lrA = __popc(m & ((1u << lane) - 1u));
    if (lane == 0) wA[w] = __popc(m);
    __syncthreads();
    if (tid == 0) { int s = 0; for (int i = 0; i < 8; i++) { wOffA[i] = s; s += wA[i]; } }
    __syncthreads();
    int nA = g_nA;
    int baseA = g_cntA[blk];
    int baseB = blk * 256 - baseA;
    int lrB   = lane - lrA;
    int wOffB = w * 32 - wOffA[w];
    int pos = cond ? (baseA + wOffA[w] + lrA)
                   : (nA + baseB + wOffB + lrB);
    g_perm[pos] = r;
}

// ------------- bucketed edge GEMM, K=256, 128x128 tile, BK=16 -----------------
// Per-output chain is k-ascending fmaf: bit-identical to the reference per-gemm
// chain. Two passes (h then v-add) reproduce "gemm1 + gemm2" exactly.
__global__ void __launch_bounds__(256)
edge_gemm(const float* __restrict__ enc, const void* __restrict__ xraw,
          const float* __restrict__ Wcond, const float* __restrict__ Wother,
          int xcol, int addmode) {
    __shared__ float As[16][132];
    __shared__ float Wsm[16][132];
    __shared__ const float* Ap[128];
    __shared__ int rowR[128];

    const int tid  = threadIdx.x;
    const int tile = blockIdx.x;
    const int col0 = blockIdx.y * 128;

    const int nA = g_nA, nB = M1 - nA;
    const int tilesA = (nA + 127) >> 7;
    const int tilesB = (nB + 127) >> 7;
    if (tile >= tilesA + tilesB) return;
    const bool bb = (tile >= tilesA);

    if (tid < 128) {
        int j   = bb ? (tile - tilesA) * 128 + tid : tile * 128 + tid;
        int cnt = bb ? nB : nA;
        int r = -1;
        const float* ap = enc;
        if (j < cnt) {
            r = g_perm[bb ? nA + j : j];
            int b = r / 5, t = r - b * 5;
            int hi, vi, tv; fetch_x(xraw, b, t, hi, vi, tv);
            int sel = xcol ? vi : hi;
            ap = enc + ((size_t)b * 7 + sel) * 256;
        }
        rowR[tid] = r; Ap[tid] = ap;
    }
    __syncthreads();

    const float* W = bb ? Wother : Wcond;
    const int lr = tid >> 2;            // 0..63
    const int kq = (tid & 3) * 4;       // 0,4,8,12
    const int tx = tid & 15, ty = tid >> 4;

    const float* a0 = Ap[lr]      + kq;
    const float* a1 = Ap[lr + 64] + kq;
    const float* w0 = W + (size_t)(col0 + lr) * 256 + kq;
    const float* w1 = W + (size_t)(col0 + lr + 64) * 256 + kq;

    float acc[8][8];
#pragma unroll
    for (int i = 0; i < 8; i++)
#pragma unroll
        for (int j = 0; j < 8; j++) acc[i][j] = 0.f;

    float4 ga0 = *(const float4*)a0;
    float4 ga1 = *(const float4*)a1;
    float4 gw0 = *(const float4*)w0;
    float4 gw1 = *(const float4*)w1;

    for (int k0 = 0; k0 < 256; k0 += 16) {
        As [kq+0][lr]    = ga0.x; As [kq+1][lr]    = ga0.y; As [kq+2][lr]    = ga0.z; As [kq+3][lr]    = ga0.w;
        As [kq+0][lr+64] = ga1.x; As [kq+1][lr+64] = ga1.y; As [kq+2][lr+64] = ga1.z; As [kq+3][lr+64] = ga1.w;
        Wsm[kq+0][lr]    = gw0.x; Wsm[kq+1][lr]    = gw0.y; Wsm[kq+2][lr]    = gw0.z; Wsm[kq+3][lr]    = gw0.w;
        Wsm[kq+0][lr+64] = gw1.x; Wsm[kq+1][lr+64] = gw1.y; Wsm[kq+2][lr+64] = gw1.z; Wsm[kq+3][lr+64] = gw1.w;
        __syncthreads();
        if (k0 < 240) {
            ga0 = *(const float4*)(a0 + k0 + 16);
            ga1 = *(const float4*)(a1 + k0 + 16);
            gw0 = *(const float4*)(w0 + k0 + 16);
            gw1 = *(const float4*)(w1 + k0 + 16);
        }
#pragma unroll
        for (int kk = 0; kk < 16; kk++) {
            float a[8], w[8];
            *(float4*)(a)     = *(const float4*)&As [kk][ty * 8];
            *(float4*)(a + 4) = *(const float4*)&As [kk][ty * 8 + 4];
            *(float4*)(w)     = *(const float4*)&Wsm[kk][tx * 4];
            *(float4*)(w + 4) = *(const float4*)&Wsm[kk][tx * 4 + 64];
#pragma unroll
            for (int i = 0; i < 8; i++)
#pragma unroll
                for (int j = 0; j < 8; j++)
                    acc[i][j] = fmaf(a[i], w[j], acc[i][j]);
        }
        __syncthreads();
    }
#pragma unroll
    for (int i = 0; i < 8; i++) {
        int r = rowR[ty * 8 + i];
        if (r < 0) continue;
        float* cp = g_E + (size_t)r * 256 + col0 + tx * 4;
        if (addmode) {
            float4 c0 = *(float4*)cp, c1 = *(float4*)(cp + 64);
            c0.x += acc[i][0]; c0.y += acc[i][1]; c0.z += acc[i][2]; c0.w += acc[i][3];
            c1.x += acc[i][4]; c1.y += acc[i][5]; c1.z += acc[i][6]; c1.w += acc[i][7];
            *(float4*)cp = c0; *(float4*)(cp + 64) = c1;
        } else {
            *(float4*)cp        = make_float4(acc[i][0], acc[i][1], acc[i][2], acc[i][3]);
            *(float4*)(cp + 64) = make_float4(acc[i][4], acc[i][5], acc[i][6], acc[i][7]);
        }
    }
}

// ------------- dense C = A @ W^T (+bias), K=256, BK=16, conflict-free ---------
__global__ void __launch_bounds__(256)
gemm256(const float* __restrict__ A, const float* __restrict__ W,
        const float* __restrict__ bias, float* __restrict__ C) {
    __shared__ float As[16][132];
    __shared__ float Wsm[16][132];
    const int tid  = threadIdx.x;
    const int row0 = blockIdx.x * 128;
    const int col0 = blockIdx.y * 128;
    const int lr = tid >> 2;
    const int kq = (tid & 3) * 4;
    const int tx = tid & 15, ty = tid >> 4;

    const float* a0 = A + (size_t)(row0 + lr) * 256 + kq;
    const float* a1 = A + (size_t)(row0 + lr + 64) * 256 + kq;
    const float* w0 = W + (size_t)(col0 + lr) * 256 + kq;
    const float* w1 = W + (size_t)(col0 + lr + 64) * 256 + kq;

    float acc[8][8];
#pragma unroll
    for (int i = 0; i < 8; i++)
#pragma unroll
        for (int j = 0; j < 8; j++) acc[i][j] = 0.f;

    float4 ga0 = *(const float4*)a0;
    float4 ga1 = *(const float4*)a1;
    float4 gw0 = *(const float4*)w0;
    float4 gw1 = *(const float4*)w1;

    for (int k0 = 0; k0 < 256; k0 += 16) {
        As [kq+0][lr]    = ga0.x; As [kq+1][lr]    = ga0.y; As [kq+2][lr]    = ga0.z; As [kq+3][lr]    = ga0.w;
        As [kq+0][lr+64] = ga1.x; As [kq+1][lr+64] = ga1.y; As [kq+2][lr+64] = ga1.z; As [kq+3][lr+64] = ga1.w;
        Wsm[kq+0][lr]    = gw0.x; Wsm[kq+1][lr]    = gw0.y; Wsm[kq+2][lr]    = gw0.z; Wsm[kq+3][lr]    = gw0.w;
        Wsm[kq+0][lr+64] = gw1.x; Wsm[kq+1][lr+64] = gw1.y; Wsm[kq+2][lr+64] = gw1.z; Wsm[kq+3][lr+64] = gw1.w;
        __syncthreads();
        if (k0 < 240) {
            ga0 = *(const float4*)(a0 + k0 + 16);
            ga1 = *(const float4*)(a1 + k0 + 16);
            gw0 = *(const float4*)(w0 + k0 + 16);
            gw1 = *(const float4*)(w1 + k0 + 16);
        }
#pragma unroll
        for (int kk = 0; kk < 16; kk++) {
            float a[8], w[8];
            *(float4*)(a)     = *(const float4*)&As [kk][ty * 8];
            *(float4*)(a + 4) = *(const float4*)&As [kk][ty * 8 + 4];
            *(float4*)(w)     = *(const float4*)&Wsm[kk][tx * 4];
            *(float4*)(w + 4) = *(const float4*)&Wsm[kk][tx * 4 + 64];
#pragma unroll
            for (int i = 0; i < 8; i++)
#pragma unroll
                for (int j = 0; j < 8; j++)
                    acc[i][j] = fmaf(a[i], w[j], acc[i][j]);
        }
        __syncthreads();
    }
    float bj[8];
#pragma unroll
    for (int j = 0; j < 4; j++) {
        bj[j]     = bias ? bias[col0 + tx * 4 + j]      : 0.f;
        bj[j + 4] = bias ? bias[col0 + tx * 4 + 64 + j] : 0.f;
    }
#pragma unroll
    for (int i = 0; i < 8; i++) {
        float* cp = C + (size_t)(row0 + ty * 8 + i) * 256 + col0 + tx * 4;
        *(float4*)cp        = make_float4(acc[i][0]+bj[0], acc[i][1]+bj[1], acc[i][2]+bj[2], acc[i][3]+bj[3]);
        *(float4*)(cp + 64) = make_float4(acc[i][4]+bj[4], acc[i][5]+bj[5], acc[i][6]+bj[6], acc[i][7]+bj[7]);
    }
}

// ------------- qt = relu(E[b,4] + max(0, Z[b,0..4])) --------------------------
__global__ void qt_kernel() {
    int i = blockIdx.x * 256 + threadIdx.x;     // over Bsz*256
    int b = i >> 8, h = i & 255;
    const float* zp = g_Z + (size_t)b * 5 * 256 + h;
    float st = fmaxf(0.f, zp[0]);
    st = fmaxf(st, zp[256]);
    st = fmaxf(st, zp[512]);
    st = fmaxf(st, zp[768]);
    st = fmaxf(st, zp[1024]);
    float e4 = g_E[(size_t)(b * 5 + 4) * 256 + h];
    g_qt[i] = fmaxf(e4 + st, 0.f);
}

// ------------- att[b,l] = 10*tanh(where(mask, sum_h V*tanh(inp+ctx), NEG)) ----
__global__ void __launch_bounds__(256)
att_kernel(const int* __restrict__ mask, const float* __restrict__ V) {
    int warp = blockIdx.x * 8 + (threadIdx.x >> 5);
    int lane = threadIdx.x & 31;
    int b = warp / 7;
    const float* ctxr = g_ctx + (size_t)warp * 256;
    const float* inpr = g_inp + (size_t)b * 256;
    float s = 0.f;
#pragma unroll
    for (int i = 0; i < 8; i++) {
        int h = i * 32 + lane;
        s += V[h] * xtanh(inpr[h] + ctxr[h]);
    }
#pragma unroll
    for (int off = 16; off > 0; off >>= 1)
        s += __shfl_down_sync(0xffffffffu, s, off);
    if (lane == 0) {
        float a = mask[warp] ? s : NEGV;
        g_att[warp] = 10.0f * xtanh(a);
    }
}

// ------------- per-column (axis=0) max and exp-sum ----------------------------
__global__ void colred() {
    int l = blockIdx.x, tid = threadIdx.x;
    __shared__ float red[256];
    float m = -3.4e38f;
    for (int b = tid; b < Bsz; b += 256) m = fmaxf(m, g_att[b * 7 + l]);
    red[tid] = m; __syncthreads();
    for (int s = 128; s > 0; s >>= 1) {
        if (tid < s) red[tid] = fmaxf(red[tid], red[tid + s]);
        __syncthreads();
    }
    float cm = red[0]; __syncthreads();
    float su = 0.f;
    for (int b = tid; b < Bsz; b += 256) su += expf(g_att[b * 7 + l] - cm);
    red[tid] = su; __syncthreads();
    for (int s = 128; s > 0; s >>= 1) {
        if (tid < s) red[tid] += red[tid + s];
        __syncthreads();
    }
    if (tid == 0) { g_cmax[l] = cm; g_csum[l] = red[0]; }
}

// ------------- alpha, gumbel, argmax, outputs ---------------------------------
__global__ void sample_kernel(const int* __restrict__ mask, float* __restrict__ out) {
    int b = blockIdx.x * 256 + threadIdx.x;
    if (b >= Bsz) return;
    float alpha[7], y[7];
#pragma unroll
    for (int l = 0; l < Lq; l++) {
        float e = expf(g_att[b * 7 + l] - g_cmax[l]);
        alpha[l] = __fdiv_rn(e, g_csum[l]);
        unsigned bits = jax_bits((unsigned)(b * 7 + l));
        float f = __uint_as_float((bits >> 9) | 0x3f800000u) - 1.0f;
        float u = (f > 0.f) ? f : 1.17549435e-38f;     // jax uniform [tiny, 1)
        float g = -logf(-logf(u));
        y[l] = g + logf(alpha[l]);
    }
    int idx = 0; float best = y[0];
#pragma unroll
    for (int l = 1; l < Lq; l++)
        if (y[l] > best) { best = y[l]; idx = l; }     // first-max like jnp.argmax
    out[b]        = (float)idx;
    out[Bsz + b]  = alpha[idx];
#pragma unroll
    for (int l = 0; l < Lq; l++)
        out[2 * Bsz + (size_t)b * 7 + l] = (float)(mask[b * 7 + l] - (l == idx ? 1 : 0));
}

// ------------- launch ---------------------------------------------------------
extern "C" void kernel_launch(void* const* d_in, const int* in_sizes, int n_in,
                              void* d_out, int out_size) {
    const float* enc  = (const float*)d_in[0];
    const void*  xes  = d_in[1];
    const int*   mask = (const int*)d_in[2];
    const float* Wh   = (const float*)d_in[3];
    const float* Wv   = (const float*)d_in[4];
    const float* Wsh  = (const float*)d_in[5];
    const float* Wsv  = (const float*)d_in[6];
    const float* We   = (const float*)d_in[7];
    const float* Win  = (const float*)d_in[8];
    const float* bin  = (const float*)d_in[9];
    const float* Wctx = (const float*)d_in[10];
    const float* bctx = (const float*)d_in[11];
    const float* V    = (const float*)d_in[12];
    float* out = (float*)d_out;

    float *pE, *pZ, *pqt, *pinp, *pctx;
    cudaGetSymbolAddress((void**)&pE,   g_E);
    cudaGetSymbolAddress((void**)&pZ,   g_Z);
    cudaGetSymbolAddress((void**)&pqt,  g_qt);
    cudaGetSymbolAddress((void**)&pinp, g_inp);
    cudaGetSymbolAddress((void**)&pctx, g_ctx);

    detect_kernel<<<1, 32>>>((const unsigned*)xes);

    // bucket rows by cond = (t==0)
    bcount  <<<NBLK, 256>>>(xes);
    bscan   <<<1, 1024>>>();
    bscatter<<<NBLK, 256>>>(xes);

    // edge passes (bit-exact vs reference: h-gemm then +v-gemm, k ascending)
    dim3 gE(M1 / 128 + 1, 2);
    edge_gemm<<<gE, 256>>>(enc, xes, Wh, Wsh, 0, 0);   // h-side
    edge_gemm<<<gE, 256>>>(enc, xes, Wv, Wsv, 1, 1);   // v-side, E += ...

    gemm256<<<dim3(M1 / 128, 2), 256>>>(pE, We, nullptr, pZ);        // Z = E @ We^T
    qt_kernel<<<Bsz, 256>>>();
    gemm256<<<dim3(Bsz / 128, 2), 256>>>(pqt, Win, bin, pinp);       // inp
    gemm256<<<dim3(BLq / 128, 2), 256>>>(enc, Wctx, bctx, pctx);     // ctx
    att_kernel<<<BLq / 8, 256>>>(mask, V);
    colred<<<Lq, 256>>>();
    sample_kernel<<<Bsz / 256, 256>>>(mask, out);
}